// round 13
// baseline (speedup 1.0000x reference)
#include <cuda_runtime.h>
#include <cuda_fp16.h>
#include <math.h>
#include <stdint.h>

// ---------------- problem dims ----------------
#define B_   4
#define L_   2048
#define DM_  1024
#define DS_  16
#define DC_  4
#define DI_  2048
#define N1_  4096              // 2*DI
#define M_   (B_ * L_)         // 8192
#define NC_  128               // padded N for the dbc GEMM
#define KZ_  4                 // K-split for dbc

// ---------------- scratch (__device__ globals, no allocation) ----------------
__device__ __half g_xinner[(size_t)M_ * N1_];    // fp16
__device__ __half g_xc16  [(size_t)M_ * DI_];    // fp16 x_conv
__device__ float g_dots  [(size_t)KZ_ * M_ * NC_];  // partial dots
__device__ float g_hc[M_ * DS_];   // h*C, s-major
__device__ __half g_xf [(size_t)M_  * DM_];
__device__ __half g_w1 [(size_t)N1_ * DM_];
__device__ __half g_wo [(size_t)DM_ * DI_];
__device__ __half g_wc [(size_t)NC_ * DI_];      // [deltaw;Bw;Cw;ones;0...]
__device__ __half g_ys [(size_t)M_  * DI_];

// ---------------- helpers ----------------
__device__ __forceinline__ uint32_t smem_u32(const void* p) {
    uint32_t a;
    asm("{ .reg .u64 t; cvta.to.shared.u64 t, %1; cvt.u32.u64 %0, t; }" : "=r"(a) : "l"(p));
    return a;
}
__device__ __forceinline__ void cp16(uint32_t dst, const void* src) {
    asm volatile("cp.async.cg.shared.global [%0], [%1], 16;" :: "r"(dst), "l"(src));
}
__device__ __forceinline__ void cp_commit() {
    asm volatile("cp.async.commit_group;" ::: "memory");
}
__device__ __forceinline__ void cp_wait1() {
    asm volatile("cp.async.wait_group 1;" ::: "memory");
}
__device__ __forceinline__ void ldm_x4(uint32_t* r, uint32_t addr) {
    asm volatile("ldmatrix.sync.aligned.m8n8.x4.shared.b16 {%0,%1,%2,%3}, [%4];"
        : "=r"(r[0]), "=r"(r[1]), "=r"(r[2]), "=r"(r[3]) : "r"(addr));
}
__device__ __forceinline__ void mma_fp16(float* c, const uint32_t* a, const uint32_t* b) {
    asm volatile(
        "mma.sync.aligned.m16n8k16.row.col.f32.f16.f16.f32 "
        "{%0,%1,%2,%3}, {%4,%5,%6,%7}, {%8,%9}, {%0,%1,%2,%3};"
        : "+f"(c[0]), "+f"(c[1]), "+f"(c[2]), "+f"(c[3])
        : "r"(a[0]), "r"(a[1]), "r"(a[2]), "r"(a[3]), "r"(b[0]), "r"(b[1]));
}

// ---------------- HMMA fp16 GEMM: C[M,*] = A[M,K] @ W[*,K]^T ----------------
// Block 128x128, k-tile 64, 8 warps, warp tile 64x32, 3-stage cp.async.
// blockIdx.z = K-split chunk (partial outputs at C + z*M*ldc).
// ldc = row stride of C (allows writing a column slice of a wider matrix).
#define BM 128
#define BN 128
#define BK 64
#define LDS_ROW 72
#define TILE_B (128 * LDS_ROW * 2)
#define STAGE_B (2 * TILE_B)
#define STAGES 3
#define SMEM_TOTAL (STAGES * STAGE_B)    // 110592

__device__ __forceinline__ void stage_load(uint32_t sbase,
    const __half* __restrict__ A, const __half* __restrict__ W,
    int k0, int lda, int tid)
{
    const __half* srcs[2] = {A, W};
    #pragma unroll
    for (int a = 0; a < 2; a++) {
        #pragma unroll
        for (int i = 0; i < 4; i++) {
            int idx = i * 256 + tid;
            int row = idx >> 3;
            int c8  = (idx & 7) * 8;
            cp16(sbase + a * TILE_B + row * (LDS_ROW * 2) + c8 * 2,
                 srcs[a] + (size_t)row * lda + k0 + c8);
        }
    }
}

template <typename TOut>
__global__ __launch_bounds__(256, 2) void gemm_tc(
    const __half* __restrict__ A, const __half* __restrict__ W,
    TOut* __restrict__ C, int M, int ldc, int lda, int Kchunk)
{
    extern __shared__ char smem[];
    uint32_t sb = smem_u32(smem);
    const int tid = threadIdx.x, wid = tid >> 5, lane = tid & 31;
    const int wm = wid >> 2, wn = wid & 3;
    const int m0 = blockIdx.y * BM, n0 = blockIdx.x * BN;

    const __half* Ap = A + (size_t)m0 * lda + (size_t)blockIdx.z * Kchunk;
    const __half* Wp = W + (size_t)n0 * lda + (size_t)blockIdx.z * Kchunk;
    TOut* Cp = C + (size_t)blockIdx.z * M * ldc;

    float acc[4][4][4];
    #pragma unroll
    for (int i = 0; i < 4; i++)
        #pragma unroll
        for (int j = 0; j < 4; j++)
            #pragma unroll
            for (int q = 0; q < 4; q++) acc[i][j][q] = 0.f;

    const int T = Kchunk / BK;
    stage_load(sb + 0 * STAGE_B, Ap, Wp, 0, lda, tid);
    cp_commit();
    stage_load(sb + 1 * STAGE_B, Ap, Wp, BK, lda, tid);
    cp_commit();

    const int l15 = lane & 15;
    const int a_khalf = (lane >> 4) & 1;
    const int b_grp = lane >> 3, b_r = lane & 7;
    const int b_row_off = ((b_grp >> 1) << 3) + b_r;
    const int b_kb = (b_grp & 1) * 16;

    for (int t = 0; t < T; t++) {
        cp_wait1();
        __syncthreads();
        if (t + 2 < T)
            stage_load(sb + ((t + 2) % STAGES) * STAGE_B, Ap, Wp,
                       (t + 2) * BK, lda, tid);
        cp_commit();

        uint32_t cur = sb + (t % STAGES) * STAGE_B;
        #pragma unroll
        for (int kk = 0; kk < 4; kk++) {
            uint32_t af[4][4], wf[2][4];
            #pragma unroll
            for (int mi = 0; mi < 4; mi++) {
                int row = wm * 64 + mi * 16 + l15;
                ldm_x4(af[mi], cur + row * (LDS_ROW * 2) + kk * 32 + a_khalf * 16);
            }
            #pragma unroll
            for (int n2 = 0; n2 < 2; n2++) {
                int row = wn * 32 + n2 * 16 + b_row_off;
                ldm_x4(wf[n2], cur + TILE_B + row * (LDS_ROW * 2) + kk * 32 + b_kb);
            }
            #pragma unroll
            for (int mi = 0; mi < 4; mi++)
                #pragma unroll
                for (int ni = 0; ni < 4; ni++)
                    mma_fp16(acc[mi][ni], af[mi], &wf[ni >> 1][(ni & 1) * 2]);
        }
    }

    const int g = lane >> 2, tq = lane & 3;
    #pragma unroll
    for (int mi = 0; mi < 4; mi++) {
        #pragma unroll
        for (int ni = 0; ni < 4; ni++) {
            int row = m0 + wm * 64 + mi * 16 + g;
            int col = n0 + wn * 32 + ni * 8 + tq * 2;
            if (sizeof(TOut) == 4) {
                *(float2*)((float*)Cp + (size_t)row * ldc + col) =
                    make_float2(acc[mi][ni][0], acc[mi][ni][1]);
                *(float2*)((float*)Cp + (size_t)(row + 8) * ldc + col) =
                    make_float2(acc[mi][ni][2], acc[mi][ni][3]);
            } else {
                __half2 h0 = __floats2half2_rn(acc[mi][ni][0], acc[mi][ni][1]);
                __half2 h1 = __floats2half2_rn(acc[mi][ni][2], acc[mi][ni][3]);
                *(uint32_t*)((__half*)Cp + (size_t)row * ldc + col) = *(uint32_t*)&h0;
                *(uint32_t*)((__half*)Cp + (size_t)(row + 8) * ldc + col) = *(uint32_t*)&h1;
            }
        }
    }
}

// ---------------- merged prep: cvt x | cvt w1 | cvt wo | build wcat --------
#define NB_X  (M_ * DM_ / 4 / 256)
#define NB_W1 (N1_ * DM_ / 4 / 256)
#define NB_WO (DM_ * DI_ / 4 / 256)
#define NB_WC (NC_ * DI_ / 4 / 256)
__global__ __launch_bounds__(256) void prep_all_kernel(
    const float* __restrict__ x, const float* __restrict__ w1,
    const float* __restrict__ wo,
    const float* __restrict__ dw, const float* __restrict__ bw,
    const float* __restrict__ cw)
{
    int blk = blockIdx.x;
    if (blk < NB_X + NB_W1 + NB_WO) {
        const float* src; __half* dst; int i;
        if (blk < NB_X) {
            src = x;  dst = g_xf;  i = blk * 256 + threadIdx.x;
        } else if (blk < NB_X + NB_W1) {
            src = w1; dst = g_w1;  i = (blk - NB_X) * 256 + threadIdx.x;
        } else {
            src = wo; dst = g_wo;  i = (blk - NB_X - NB_W1) * 256 + threadIdx.x;
        }
        float4 v = ((const float4*)src)[i];
        __half2 a = __floats2half2_rn(v.x, v.y);
        __half2 b = __floats2half2_rn(v.z, v.w);
        ((uint2*)dst)[i] = make_uint2(*(uint32_t*)&a, *(uint32_t*)&b);
    } else {
        int i = (blk - NB_X - NB_W1 - NB_WO) * 256 + threadIdx.x;
        int row = i / (DI_ / 4);
        int c4  = (i % (DI_ / 4)) * 4;
        float4 v;
        if (row < 16)       v = *(const float4*)(dw + (size_t)row * DI_ + c4);
        else if (row < 32)  v = *(const float4*)(bw + (size_t)(row - 16) * DI_ + c4);
        else if (row < 48)  v = *(const float4*)(cw + (size_t)(row - 32) * DI_ + c4);
        else if (row == 48) v = make_float4(1.f, 1.f, 1.f, 1.f);
        else                v = make_float4(0.f, 0.f, 0.f, 0.f);
        __half2 a = __floats2half2_rn(v.x, v.y);
        __half2 b = __floats2half2_rn(v.z, v.w);
        ((uint2*)g_wc)[i] = make_uint2(*(uint32_t*)&a, *(uint32_t*)&b);
    }
}

// ---------------- causal conv (DC=4) + silu, 4-l blocking, fp16 in/out ------
__global__ __launch_bounds__(256) void conv_silu_kernel(
    const float* __restrict__ cw, const float* __restrict__ cb)
{
    int gid = blockIdx.x * blockDim.x + threadIdx.x;
    if (gid >= (M_ / 4) * (DI_ / 4)) return;
    int iq = gid & (DI_ / 4 - 1);
    int rq = gid >> 9;
    int i  = iq * 4;
    int b  = rq >> 9;
    int l0 = (rq & 511) * 4;

    float4 bias = *(const float4*)(cb + i);
    float w[4][4];
    #pragma unroll
    for (int j = 0; j < 4; j++) {
        float4 t = *(const float4*)(cw + (i + j) * DC_);
        w[j][0] = t.x; w[j][1] = t.y; w[j][2] = t.z; w[j][3] = t.w;
    }

    float v[7][4];
    #pragma unroll
    for (int j = 0; j < 7; j++) {
        int ls = l0 + j - 3;
        if (ls >= 0) {
            uint2 raw = *(const uint2*)(g_xinner + (size_t)(b * L_ + ls) * N1_ + i);
            float2 a0 = __half22float2(*(__half2*)&raw.x);
            float2 a1 = __half22float2(*(__half2*)&raw.y);
            v[j][0] = a0.x; v[j][1] = a0.y; v[j][2] = a1.x; v[j][3] = a1.y;
        } else {
            v[j][0] = v[j][1] = v[j][2] = v[j][3] = 0.f;
        }
    }

    #pragma unroll
    for (int t = 0; t < 4; t++) {
        float acc[4] = {bias.x, bias.y, bias.z, bias.w};
        #pragma unroll
        for (int k = 0; k < DC_; k++) {
            acc[0] = fmaf(v[t + k][0], w[0][k], acc[0]);
            acc[1] = fmaf(v[t + k][1], w[1][k], acc[1]);
            acc[2] = fmaf(v[t + k][2], w[2][k], acc[2]);
            acc[3] = fmaf(v[t + k][3], w[3][k], acc[3]);
        }
        float f0 = acc[0] / (1.f + expf(-acc[0]));
        float f1 = acc[1] / (1.f + expf(-acc[1]));
        float f2 = acc[2] / (1.f + expf(-acc[2]));
        float f3 = acc[3] / (1.f + expf(-acc[3]));
        __half2 a = __floats2half2_rn(f0, f1);
        __half2 bb = __floats2half2_rn(f2, f3);
        size_t o = (size_t)(b * L_ + l0 + t) * (DI_ / 4) + iq;
        ((uint2*)g_xc16)[o] = make_uint2(*(uint32_t*)&a, *(uint32_t*)&bb);
    }
}

// ---------------- scan (gu fused): one block per (b,s), 128 threads ---------
__global__ __launch_bounds__(128) void scan2_kernel(
    const float* __restrict__ A_log, const float* __restrict__ delta_b)
{
    __shared__ float sG[L_], sU[L_], sC[L_];
    __shared__ float sA[128], sB[128];
    const int b = blockIdx.x >> 4, s = blockIdx.x & 15;
    const int tid = threadIdx.x;

    const float Aval = -expf(A_log[s]);
    const float dbias = delta_b[s];

    for (int l = tid; l < L_; l += 128) {
        size_t ro = (size_t)(b * L_ + l) * NC_;
        float dd = 0.f, db = 0.f, dc = 0.f, rs = 0.f;
        #pragma unroll
        for (int p = 0; p < KZ_; p++) {
            const float* dp = g_dots + (size_t)p * M_ * NC_ + ro;
            dd += dp[s];
            db += dp[16 + s];
            dc += dp[32 + s];
            rs += dp[48];
        }
        float z = dd + dbias;
        float delta = (z > 20.f) ? z : log1pf(expf(z));
        sG[l] = expf(delta * Aval);
        sU[l] = delta * db * (rs * (1.f / (float)DI_));
        sC[l] = dc;
    }
    __syncthreads();

    const int CH = L_ / 128;   // 16
    const int l0 = tid * CH;
    float A = 1.f, U = 0.f;
    #pragma unroll
    for (int i = 0; i < CH; i++) {
        float gv = sG[l0 + i];
        A *= gv;
        U = fmaf(gv, U, sU[l0 + i]);
    }
    sA[tid] = A; sB[tid] = U;
    __syncthreads();

    #pragma unroll
    for (int d = 1; d < 128; d <<= 1) {
        float a2 = sA[tid], u2 = sB[tid];
        float a1 = 1.f, u1 = 0.f;
        if (tid >= d) { a1 = sA[tid - d]; u1 = sB[tid - d]; }
        __syncthreads();
        sA[tid] = a2 * a1;
        sB[tid] = fmaf(a2, u1, u2);
        __syncthreads();
    }

    float h = (tid == 0) ? 0.f : sB[tid - 1];
    #pragma unroll
    for (int i = 0; i < CH; i++) {
        h = fmaf(sG[l0 + i], h, sU[l0 + i]);
        sU[l0 + i] = h * sC[l0 + i];
    }
    __syncthreads();
    const size_t base = (size_t)s * M_ + (size_t)b * L_;
    for (int i = tid; i < L_ / 4; i += 128)
        *(float4*)(g_hc + base + i * 4) = ((float4*)sU)[i];
}

// ---------------- yskip (fused ysum): one 512-thread block per row ----------
__global__ __launch_bounds__(512) void yskip_kernel(const float* __restrict__ Dp)
{
    __shared__ float ysh;
    const int r = blockIdx.x;
    const int tid = threadIdx.x;

    if (tid < 16) {
        float v = g_hc[(size_t)tid * M_ + r];
        #pragma unroll
        for (int o = 8; o >= 1; o >>= 1)
            v += __shfl_xor_sync(0x0000ffffu, v, o);
        if (tid == 0) ysh = v;
    }
    __syncthreads();
    float yv = ysh;

    int i = tid * 4;
    uint2 graw = *(const uint2*)(g_xinner + (size_t)r * N1_ + DI_ + i);
    float2 g0 = __half22float2(*(__half2*)&graw.x);
    float2 g1 = __half22float2(*(__half2*)&graw.y);
    uint2 xraw = ((const uint2*)g_xc16)[(size_t)r * (DI_ / 4) + tid];
    float2 x0 = __half22float2(*(__half2*)&xraw.x);
    float2 x1 = __half22float2(*(__half2*)&xraw.y);
    float4 dv = *(const float4*)(Dp + i);
    float f0 = fmaf(yv, g0.x / (1.f + expf(-g0.x)), x0.x * dv.x);
    float f1 = fmaf(yv, g0.y / (1.f + expf(-g0.y)), x0.y * dv.y);
    float f2 = fmaf(yv, g1.x / (1.f + expf(-g1.x)), x1.x * dv.z);
    float f3 = fmaf(yv, g1.y / (1.f + expf(-g1.y)), x1.y * dv.w);
    __half2 a = __floats2half2_rn(f0, f1);
    __half2 b = __floats2half2_rn(f2, f3);
    ((uint2*)g_ys)[(size_t)r * (DI_ / 4) + tid] = make_uint2(*(uint32_t*)&a, *(uint32_t*)&b);
}

// ---------------- launch ----------------
extern "C" void kernel_launch(void* const* d_in, const int* in_sizes, int n_in,
                              void* d_out, int out_size)
{
    const float* x          = (const float*)d_in[0];
    const float* in_proj_w  = (const float*)d_in[1];
    const float* conv_w     = (const float*)d_in[2];
    const float* conv_b     = (const float*)d_in[3];
    const float* A_log      = (const float*)d_in[4];
    const float* Dp         = (const float*)d_in[5];
    const float* delta_w    = (const float*)d_in[6];
    const float* delta_b    = (const float*)d_in[7];
    const float* B_w        = (const float*)d_in[8];
    const float* C_w        = (const float*)d_in[9];
    const float* out_proj_w = (const float*)d_in[10];
    float* out = (float*)d_out;

    __half *p_xinner, *p_xf, *p_w1, *p_wo, *p_wc, *p_ys, *p_xc16;
    float *p_dots;
    cudaGetSymbolAddress((void**)&p_xinner, g_xinner);
    cudaGetSymbolAddress((void**)&p_xf, g_xf);
    cudaGetSymbolAddress((void**)&p_w1, g_w1);
    cudaGetSymbolAddress((void**)&p_wo, g_wo);
    cudaGetSymbolAddress((void**)&p_wc, g_wc);
    cudaGetSymbolAddress((void**)&p_ys, g_ys);
    cudaGetSymbolAddress((void**)&p_xc16, g_xc16);
    cudaGetSymbolAddress((void**)&p_dots, g_dots);

    // Lazy one-time setup. First call is the uncaptured correctness run,
    // so stream/event creation never happens during graph capture.
    static cudaStream_t s1 = nullptr;
    static cudaEvent_t e_a = nullptr, e_s = nullptr;
    static bool inited = false;
    if (!inited) {
        cudaStreamCreateWithFlags(&s1, cudaStreamNonBlocking);
        cudaEventCreateWithFlags(&e_a, cudaEventDisableTiming);
        cudaEventCreateWithFlags(&e_s, cudaEventDisableTiming);
        cudaFuncSetAttribute(gemm_tc<__half>, cudaFuncAttributeMaxDynamicSharedMemorySize, SMEM_TOTAL);
        cudaFuncSetAttribute(gemm_tc<float>,  cudaFuncAttributeMaxDynamicSharedMemorySize, SMEM_TOTAL);
        inited = true;
    }

    // 0) all prep in one kernel (implicit capture stream 0)
    prep_all_kernel<<<NB_X + NB_W1 + NB_WO + NB_WC, 256>>>(
        x, in_proj_w, out_proj_w, delta_w, B_w, C_w);

    // 1a) ssm half: x_inner[:, 0:2048]
    gemm_tc<__half><<<dim3(DI_ / BN, M_ / BM, 1), 256, SMEM_TOTAL>>>(
        p_xf, p_w1, p_xinner, M_, N1_, DM_, DM_);
    cudaEventRecord(e_a, 0);

    // 1b) gate half: x_inner[:, 2048:4096] (queued right after 1a)
    gemm_tc<__half><<<dim3(DI_ / BN, M_ / BM, 1), 256, SMEM_TOTAL>>>(
        p_xf, p_w1 + (size_t)DI_ * DM_, p_xinner + DI_, M_, N1_, DM_, DM_);

    // --- fork: conv -> dbc -> scan on s1, overlapping GEMM1b ---
    cudaStreamWaitEvent(s1, e_a, 0);
    conv_silu_kernel<<<((M_ / 4) * (DI_ / 4) + 255) / 256, 256, 0, s1>>>(conv_w, conv_b);
    gemm_tc<float><<<dim3(1, M_ / BM, KZ_), 256, SMEM_TOTAL, s1>>>(
        p_xc16, p_wc, p_dots, M_, NC_, DI_, DI_ / KZ_);
    scan2_kernel<<<B_ * DS_, 128, 0, s1>>>(A_log, delta_b);
    cudaEventRecord(e_s, s1);

    // --- join back on the capture stream ---
    cudaStreamWaitEvent(0, e_s, 0);

    // 2) gate + skip fuse (needs gate half + scan) -> fp16
    yskip_kernel<<<M_, 512>>>(Dp);

    // 3) out = y_skip @ out_proj_w^T  [8192,1024]  (fp32 out)
    gemm_tc<float><<<dim3(DM_ / BN, M_ / BM, 1), 256, SMEM_TOTAL>>>(
        p_ys, p_wo, out, M_, DM_, DI_, DI_);
}

// round 14
// speedup vs baseline: 1.0067x; 1.0067x over previous
#include <cuda_runtime.h>
#include <cuda_fp16.h>
#include <math.h>
#include <stdint.h>

// ---------------- problem dims ----------------
#define B_   4
#define L_   2048
#define DM_  1024
#define DS_  16
#define DC_  4
#define DI_  2048
#define N1_  4096              // 2*DI
#define M_   (B_ * L_)         // 8192
#define NC_  128               // padded N for the dbc GEMM
#define KZ_  4                 // K-split for dbc

// ---------------- scratch (__device__ globals, no allocation) ----------------
__device__ __half g_xinner[(size_t)M_ * N1_];    // fp16
__device__ __half g_xc16  [(size_t)M_ * DI_];    // fp16 x_conv
__device__ float g_dots  [(size_t)KZ_ * M_ * NC_];  // partial dots
__device__ float g_hc[M_ * DS_];   // h*C, s-major
__device__ __half g_xf [(size_t)M_  * DM_];
__device__ __half g_w1 [(size_t)N1_ * DM_];
__device__ __half g_wo [(size_t)DM_ * DI_];
__device__ __half g_wc [(size_t)NC_ * DI_];      // [deltaw;Bw;Cw;ones;0...]
__device__ __half g_ys [(size_t)M_  * DI_];

// ---------------- helpers ----------------
__device__ __forceinline__ uint32_t smem_u32(const void* p) {
    uint32_t a;
    asm("{ .reg .u64 t; cvta.to.shared.u64 t, %1; cvt.u32.u64 %0, t; }" : "=r"(a) : "l"(p));
    return a;
}
__device__ __forceinline__ void cp16(uint32_t dst, const void* src) {
    asm volatile("cp.async.cg.shared.global [%0], [%1], 16;" :: "r"(dst), "l"(src));
}
__device__ __forceinline__ void cp_commit() {
    asm volatile("cp.async.commit_group;" ::: "memory");
}
__device__ __forceinline__ void cp_wait1() {
    asm volatile("cp.async.wait_group 1;" ::: "memory");
}
__device__ __forceinline__ void ldm_x4(uint32_t* r, uint32_t addr) {
    asm volatile("ldmatrix.sync.aligned.m8n8.x4.shared.b16 {%0,%1,%2,%3}, [%4];"
        : "=r"(r[0]), "=r"(r[1]), "=r"(r[2]), "=r"(r[3]) : "r"(addr));
}
__device__ __forceinline__ void mma_fp16(float* c, const uint32_t* a, const uint32_t* b) {
    asm volatile(
        "mma.sync.aligned.m16n8k16.row.col.f32.f16.f16.f32 "
        "{%0,%1,%2,%3}, {%4,%5,%6,%7}, {%8,%9}, {%0,%1,%2,%3};"
        : "+f"(c[0]), "+f"(c[1]), "+f"(c[2]), "+f"(c[3])
        : "r"(a[0]), "r"(a[1]), "r"(a[2]), "r"(a[3]), "r"(b[0]), "r"(b[1]));
}
__device__ __forceinline__ float fast_sigmoid(float v) {
    return 1.f / (1.f + __expf(-v));
}

// ---------------- HMMA fp16 GEMM: C[M,*] = A[M,K] @ W[*,K]^T ----------------
// Block 128x128, k-tile 64, 8 warps, warp tile 64x32, 3-stage cp.async.
// blockIdx.z = K-split chunk (partial outputs at C + z*M*ldc).
#define BM 128
#define BN 128
#define BK 64
#define LDS_ROW 72
#define TILE_B (128 * LDS_ROW * 2)
#define STAGE_B (2 * TILE_B)
#define STAGES 3
#define SMEM_TOTAL (STAGES * STAGE_B)    // 110592

__device__ __forceinline__ void stage_load(uint32_t sbase,
    const __half* __restrict__ A, const __half* __restrict__ W,
    int k0, int lda, int tid)
{
    const __half* srcs[2] = {A, W};
    #pragma unroll
    for (int a = 0; a < 2; a++) {
        #pragma unroll
        for (int i = 0; i < 4; i++) {
            int idx = i * 256 + tid;
            int row = idx >> 3;
            int c8  = (idx & 7) * 8;
            cp16(sbase + a * TILE_B + row * (LDS_ROW * 2) + c8 * 2,
                 srcs[a] + (size_t)row * lda + k0 + c8);
        }
    }
}

template <typename TOut>
__global__ __launch_bounds__(256, 2) void gemm_tc(
    const __half* __restrict__ A, const __half* __restrict__ W,
    TOut* __restrict__ C, int M, int ldc, int lda, int Kchunk)
{
    extern __shared__ char smem[];
    uint32_t sb = smem_u32(smem);
    const int tid = threadIdx.x, wid = tid >> 5, lane = tid & 31;
    const int wm = wid >> 2, wn = wid & 3;
    const int m0 = blockIdx.y * BM, n0 = blockIdx.x * BN;

    const __half* Ap = A + (size_t)m0 * lda + (size_t)blockIdx.z * Kchunk;
    const __half* Wp = W + (size_t)n0 * lda + (size_t)blockIdx.z * Kchunk;
    TOut* Cp = C + (size_t)blockIdx.z * M * ldc;

    float acc[4][4][4];
    #pragma unroll
    for (int i = 0; i < 4; i++)
        #pragma unroll
        for (int j = 0; j < 4; j++)
            #pragma unroll
            for (int q = 0; q < 4; q++) acc[i][j][q] = 0.f;

    const int T = Kchunk / BK;
    stage_load(sb + 0 * STAGE_B, Ap, Wp, 0, lda, tid);
    cp_commit();
    stage_load(sb + 1 * STAGE_B, Ap, Wp, BK, lda, tid);
    cp_commit();

    const int l15 = lane & 15;
    const int a_khalf = (lane >> 4) & 1;
    const int b_grp = lane >> 3, b_r = lane & 7;
    const int b_row_off = ((b_grp >> 1) << 3) + b_r;
    const int b_kb = (b_grp & 1) * 16;

    for (int t = 0; t < T; t++) {
        cp_wait1();
        __syncthreads();
        if (t + 2 < T)
            stage_load(sb + ((t + 2) % STAGES) * STAGE_B, Ap, Wp,
                       (t + 2) * BK, lda, tid);
        cp_commit();

        uint32_t cur = sb + (t % STAGES) * STAGE_B;
        #pragma unroll
        for (int kk = 0; kk < 4; kk++) {
            uint32_t af[4][4], wf[2][4];
            #pragma unroll
            for (int mi = 0; mi < 4; mi++) {
                int row = wm * 64 + mi * 16 + l15;
                ldm_x4(af[mi], cur + row * (LDS_ROW * 2) + kk * 32 + a_khalf * 16);
            }
            #pragma unroll
            for (int n2 = 0; n2 < 2; n2++) {
                int row = wn * 32 + n2 * 16 + b_row_off;
                ldm_x4(wf[n2], cur + TILE_B + row * (LDS_ROW * 2) + kk * 32 + b_kb);
            }
            #pragma unroll
            for (int mi = 0; mi < 4; mi++)
                #pragma unroll
                for (int ni = 0; ni < 4; ni++)
                    mma_fp16(acc[mi][ni], af[mi], &wf[ni >> 1][(ni & 1) * 2]);
        }
    }

    const int g = lane >> 2, tq = lane & 3;
    #pragma unroll
    for (int mi = 0; mi < 4; mi++) {
        #pragma unroll
        for (int ni = 0; ni < 4; ni++) {
            int row = m0 + wm * 64 + mi * 16 + g;
            int col = n0 + wn * 32 + ni * 8 + tq * 2;
            if (sizeof(TOut) == 4) {
                *(float2*)((float*)Cp + (size_t)row * ldc + col) =
                    make_float2(acc[mi][ni][0], acc[mi][ni][1]);
                *(float2*)((float*)Cp + (size_t)(row + 8) * ldc + col) =
                    make_float2(acc[mi][ni][2], acc[mi][ni][3]);
            } else {
                __half2 h0 = __floats2half2_rn(acc[mi][ni][0], acc[mi][ni][1]);
                __half2 h1 = __floats2half2_rn(acc[mi][ni][2], acc[mi][ni][3]);
                *(uint32_t*)((__half*)Cp + (size_t)row * ldc + col) = *(uint32_t*)&h0;
                *(uint32_t*)((__half*)Cp + (size_t)(row + 8) * ldc + col) = *(uint32_t*)&h1;
            }
        }
    }
}

// ---------------- merged prep: cvt x | cvt w1 | cvt wo | build wcat --------
#define NB_X  (M_ * DM_ / 4 / 256)
#define NB_W1 (N1_ * DM_ / 4 / 256)
#define NB_WO (DM_ * DI_ / 4 / 256)
#define NB_WC (NC_ * DI_ / 4 / 256)
__global__ __launch_bounds__(256) void prep_all_kernel(
    const float* __restrict__ x, const float* __restrict__ w1,
    const float* __restrict__ wo,
    const float* __restrict__ dw, const float* __restrict__ bw,
    const float* __restrict__ cw)
{
    int blk = blockIdx.x;
    if (blk < NB_X + NB_W1 + NB_WO) {
        const float* src; __half* dst; int i;
        if (blk < NB_X) {
            src = x;  dst = g_xf;  i = blk * 256 + threadIdx.x;
        } else if (blk < NB_X + NB_W1) {
            src = w1; dst = g_w1;  i = (blk - NB_X) * 256 + threadIdx.x;
        } else {
            src = wo; dst = g_wo;  i = (blk - NB_X - NB_W1) * 256 + threadIdx.x;
        }
        float4 v = ((const float4*)src)[i];
        __half2 a = __floats2half2_rn(v.x, v.y);
        __half2 b = __floats2half2_rn(v.z, v.w);
        ((uint2*)dst)[i] = make_uint2(*(uint32_t*)&a, *(uint32_t*)&b);
    } else {
        int i = (blk - NB_X - NB_W1 - NB_WO) * 256 + threadIdx.x;
        int row = i / (DI_ / 4);
        int c4  = (i % (DI_ / 4)) * 4;
        float4 v;
        if (row < 16)       v = *(const float4*)(dw + (size_t)row * DI_ + c4);
        else if (row < 32)  v = *(const float4*)(bw + (size_t)(row - 16) * DI_ + c4);
        else if (row < 48)  v = *(const float4*)(cw + (size_t)(row - 32) * DI_ + c4);
        else if (row == 48) v = make_float4(1.f, 1.f, 1.f, 1.f);
        else                v = make_float4(0.f, 0.f, 0.f, 0.f);
        __half2 a = __floats2half2_rn(v.x, v.y);
        __half2 b = __floats2half2_rn(v.z, v.w);
        ((uint2*)g_wc)[i] = make_uint2(*(uint32_t*)&a, *(uint32_t*)&b);
    }
}

// ---------------- causal conv (DC=4) + silu, 4-l blocking, fp16 in/out ------
__global__ __launch_bounds__(256) void conv_silu_kernel(
    const float* __restrict__ cw, const float* __restrict__ cb)
{
    int gid = blockIdx.x * blockDim.x + threadIdx.x;
    if (gid >= (M_ / 4) * (DI_ / 4)) return;
    int iq = gid & (DI_ / 4 - 1);
    int rq = gid >> 9;
    int i  = iq * 4;
    int b  = rq >> 9;
    int l0 = (rq & 511) * 4;

    float4 bias = *(const float4*)(cb + i);
    float w[4][4];
    #pragma unroll
    for (int j = 0; j < 4; j++) {
        float4 t = *(const float4*)(cw + (i + j) * DC_);
        w[j][0] = t.x; w[j][1] = t.y; w[j][2] = t.z; w[j][3] = t.w;
    }

    float v[7][4];
    #pragma unroll
    for (int j = 0; j < 7; j++) {
        int ls = l0 + j - 3;
        if (ls >= 0) {
            uint2 raw = *(const uint2*)(g_xinner + (size_t)(b * L_ + ls) * N1_ + i);
            float2 a0 = __half22float2(*(__half2*)&raw.x);
            float2 a1 = __half22float2(*(__half2*)&raw.y);
            v[j][0] = a0.x; v[j][1] = a0.y; v[j][2] = a1.x; v[j][3] = a1.y;
        } else {
            v[j][0] = v[j][1] = v[j][2] = v[j][3] = 0.f;
        }
    }

    #pragma unroll
    for (int t = 0; t < 4; t++) {
        float acc[4] = {bias.x, bias.y, bias.z, bias.w};
        #pragma unroll
        for (int k = 0; k < DC_; k++) {
            acc[0] = fmaf(v[t + k][0], w[0][k], acc[0]);
            acc[1] = fmaf(v[t + k][1], w[1][k], acc[1]);
            acc[2] = fmaf(v[t + k][2], w[2][k], acc[2]);
            acc[3] = fmaf(v[t + k][3], w[3][k], acc[3]);
        }
        float f0 = acc[0] * fast_sigmoid(acc[0]);
        float f1 = acc[1] * fast_sigmoid(acc[1]);
        float f2 = acc[2] * fast_sigmoid(acc[2]);
        float f3 = acc[3] * fast_sigmoid(acc[3]);
        __half2 a = __floats2half2_rn(f0, f1);
        __half2 bb = __floats2half2_rn(f2, f3);
        size_t o = (size_t)(b * L_ + l0 + t) * (DI_ / 4) + iq;
        ((uint2*)g_xc16)[o] = make_uint2(*(uint32_t*)&a, *(uint32_t*)&bb);
    }
}

// ---------------- scan (gu fused): one block per (b,s), 128 threads ---------
__global__ __launch_bounds__(128) void scan2_kernel(
    const float* __restrict__ A_log, const float* __restrict__ delta_b)
{
    __shared__ float sG[L_], sU[L_], sC[L_];
    __shared__ float sA[128], sB[128];
    const int b = blockIdx.x >> 4, s = blockIdx.x & 15;
    const int tid = threadIdx.x;

    const float Aval = -expf(A_log[s]);
    const float dbias = delta_b[s];

    for (int l = tid; l < L_; l += 128) {
        size_t ro = (size_t)(b * L_ + l) * NC_;
        float dd = 0.f, db = 0.f, dc = 0.f, rs = 0.f;
        #pragma unroll
        for (int p = 0; p < KZ_; p++) {
            const float* dp = g_dots + (size_t)p * M_ * NC_ + ro;
            dd += dp[s];
            db += dp[16 + s];
            dc += dp[32 + s];
            rs += dp[48];
        }
        float z = dd + dbias;
        float delta = (z > 20.f) ? z : log1pf(expf(z));
        sG[l] = expf(delta * Aval);
        sU[l] = delta * db * (rs * (1.f / (float)DI_));
        sC[l] = dc;
    }
    __syncthreads();

    const int CH = L_ / 128;   // 16
    const int l0 = tid * CH;
    float A = 1.f, U = 0.f;
    #pragma unroll
    for (int i = 0; i < CH; i++) {
        float gv = sG[l0 + i];
        A *= gv;
        U = fmaf(gv, U, sU[l0 + i]);
    }
    sA[tid] = A; sB[tid] = U;
    __syncthreads();

    #pragma unroll
    for (int d = 1; d < 128; d <<= 1) {
        float a2 = sA[tid], u2 = sB[tid];
        float a1 = 1.f, u1 = 0.f;
        if (tid >= d) { a1 = sA[tid - d]; u1 = sB[tid - d]; }
        __syncthreads();
        sA[tid] = a2 * a1;
        sB[tid] = fmaf(a2, u1, u2);
        __syncthreads();
    }

    float h = (tid == 0) ? 0.f : sB[tid - 1];
    #pragma unroll
    for (int i = 0; i < CH; i++) {
        h = fmaf(sG[l0 + i], h, sU[l0 + i]);
        sU[l0 + i] = h * sC[l0 + i];
    }
    __syncthreads();
    const size_t base = (size_t)s * M_ + (size_t)b * L_;
    for (int i = tid; i < L_ / 4; i += 128)
        *(float4*)(g_hc + base + i * 4) = ((float4*)sU)[i];
}

// ---------------- yskip (fused ysum): one 512-thread block per row ----------
__global__ __launch_bounds__(512) void yskip_kernel(const float* __restrict__ Dp)
{
    __shared__ float ysh;
    const int r = blockIdx.x;
    const int tid = threadIdx.x;

    if (tid < 16) {
        float v = g_hc[(size_t)tid * M_ + r];
        #pragma unroll
        for (int o = 8; o >= 1; o >>= 1)
            v += __shfl_xor_sync(0x0000ffffu, v, o);
        if (tid == 0) ysh = v;
    }
    __syncthreads();
    float yv = ysh;

    int i = tid * 4;
    uint2 graw = *(const uint2*)(g_xinner + (size_t)r * N1_ + DI_ + i);
    float2 g0 = __half22float2(*(__half2*)&graw.x);
    float2 g1 = __half22float2(*(__half2*)&graw.y);
    uint2 xraw = ((const uint2*)g_xc16)[(size_t)r * (DI_ / 4) + tid];
    float2 x0 = __half22float2(*(__half2*)&xraw.x);
    float2 x1 = __half22float2(*(__half2*)&xraw.y);
    float4 dv = *(const float4*)(Dp + i);
    float f0 = fmaf(yv, g0.x * fast_sigmoid(g0.x), x0.x * dv.x);
    float f1 = fmaf(yv, g0.y * fast_sigmoid(g0.y), x0.y * dv.y);
    float f2 = fmaf(yv, g1.x * fast_sigmoid(g1.x), x1.x * dv.z);
    float f3 = fmaf(yv, g1.y * fast_sigmoid(g1.y), x1.y * dv.w);
    __half2 a = __floats2half2_rn(f0, f1);
    __half2 b = __floats2half2_rn(f2, f3);
    ((uint2*)g_ys)[(size_t)r * (DI_ / 4) + tid] = make_uint2(*(uint32_t*)&a, *(uint32_t*)&b);
}

// ---------------- launch ----------------
extern "C" void kernel_launch(void* const* d_in, const int* in_sizes, int n_in,
                              void* d_out, int out_size)
{
    const float* x          = (const float*)d_in[0];
    const float* in_proj_w  = (const float*)d_in[1];
    const float* conv_w     = (const float*)d_in[2];
    const float* conv_b     = (const float*)d_in[3];
    const float* A_log      = (const float*)d_in[4];
    const float* Dp         = (const float*)d_in[5];
    const float* delta_w    = (const float*)d_in[6];
    const float* delta_b    = (const float*)d_in[7];
    const float* B_w        = (const float*)d_in[8];
    const float* C_w        = (const float*)d_in[9];
    const float* out_proj_w = (const float*)d_in[10];
    float* out = (float*)d_out;

    __half *p_xinner, *p_xf, *p_w1, *p_wo, *p_wc, *p_ys, *p_xc16;
    float *p_dots;
    cudaGetSymbolAddress((void**)&p_xinner, g_xinner);
    cudaGetSymbolAddress((void**)&p_xf, g_xf);
    cudaGetSymbolAddress((void**)&p_w1, g_w1);
    cudaGetSymbolAddress((void**)&p_wo, g_wo);
    cudaGetSymbolAddress((void**)&p_wc, g_wc);
    cudaGetSymbolAddress((void**)&p_ys, g_ys);
    cudaGetSymbolAddress((void**)&p_xc16, g_xc16);
    cudaGetSymbolAddress((void**)&p_dots, g_dots);

    cudaFuncSetAttribute(gemm_tc<__half>, cudaFuncAttributeMaxDynamicSharedMemorySize, SMEM_TOTAL);
    cudaFuncSetAttribute(gemm_tc<float>,  cudaFuncAttributeMaxDynamicSharedMemorySize, SMEM_TOTAL);

    // 0) all prep in one kernel
    prep_all_kernel<<<NB_X + NB_W1 + NB_WO + NB_WC, 256>>>(
        x, in_proj_w, out_proj_w, delta_w, B_w, C_w);

    // 1) x_inner = x @ in_proj_w^T  [8192,4096]  (fp16 out)
    gemm_tc<__half><<<dim3(N1_ / BN, M_ / BM, 1), 256, SMEM_TOTAL>>>(
        p_xf, p_w1, p_xinner, M_, N1_, DM_, DM_);

    // 2) causal conv + silu (fp16 in/out, 4-l blocking)
    conv_silu_kernel<<<((M_ / 4) * (DI_ / 4) + 255) / 256, 256>>>(conv_w, conv_b);

    // 3) dots = x_conv @ wcat^T  [8192,128], K-split z=4 (partials)
    gemm_tc<float><<<dim3(1, M_ / BM, KZ_), 256, SMEM_TOTAL>>>(
        p_xc16, p_wc, p_dots, M_, NC_, DI_, DI_ / KZ_);

    // 4) scan (coefficient computation fused)
    scan2_kernel<<<B_ * DS_, 128>>>(A_log, delta_b);

    // 5) gate + skip fuse (ysum inlined) -> fp16
    yskip_kernel<<<M_, 512>>>(Dp);

    // 6) out = y_skip @ out_proj_w^T  [8192,1024]  (fp32 out)
    gemm_tc<float><<<dim3(DM_ / BN, M_ / BM, 1), 256, SMEM_TOTAL>>>(
        p_ys, p_wo, out, M_, DM_, DI_, DI_);
}

// round 15
// speedup vs baseline: 1.0595x; 1.0524x over previous
#include <cuda_runtime.h>
#include <cuda_fp16.h>
#include <math.h>
#include <stdint.h>

// ---------------- problem dims ----------------
#define B_   4
#define L_   2048
#define DM_  1024
#define DS_  16
#define DC_  4
#define DI_  2048
#define N1_  4096              // 2*DI
#define M_   (B_ * L_)         // 8192
#define NC_  128               // padded N for the dbc GEMM
#define KZ_  2                 // K-split for dbc (R14 showed 4 is worse)

// ---------------- scratch (__device__ globals, no allocation) ----------------
__device__ __half g_xinner[(size_t)M_ * N1_];    // fp16
__device__ __half g_xc16  [(size_t)M_ * DI_];    // fp16 x_conv
__device__ float g_dots  [(size_t)KZ_ * M_ * NC_];  // partial dots
__device__ float g_hc[M_ * DS_];   // h*C, s-major
__device__ __half g_xf [(size_t)M_  * DM_];
__device__ __half g_w1 [(size_t)N1_ * DM_];
__device__ __half g_wo [(size_t)DM_ * DI_];
__device__ __half g_wc [(size_t)NC_ * DI_];      // [deltaw;Bw;Cw;ones;0...]
__device__ __half g_ys [(size_t)M_  * DI_];

// ---------------- helpers ----------------
__device__ __forceinline__ uint32_t smem_u32(const void* p) {
    uint32_t a;
    asm("{ .reg .u64 t; cvta.to.shared.u64 t, %1; cvt.u32.u64 %0, t; }" : "=r"(a) : "l"(p));
    return a;
}
__device__ __forceinline__ void cp16(uint32_t dst, const void* src) {
    asm volatile("cp.async.cg.shared.global [%0], [%1], 16;" :: "r"(dst), "l"(src));
}
__device__ __forceinline__ void cp_commit() {
    asm volatile("cp.async.commit_group;" ::: "memory");
}
__device__ __forceinline__ void cp_wait1() {
    asm volatile("cp.async.wait_group 1;" ::: "memory");
}
__device__ __forceinline__ void ldm_x4(uint32_t* r, uint32_t addr) {
    asm volatile("ldmatrix.sync.aligned.m8n8.x4.shared.b16 {%0,%1,%2,%3}, [%4];"
        : "=r"(r[0]), "=r"(r[1]), "=r"(r[2]), "=r"(r[3]) : "r"(addr));
}
__device__ __forceinline__ void mma_fp16(float* c, const uint32_t* a, const uint32_t* b) {
    asm volatile(
        "mma.sync.aligned.m16n8k16.row.col.f32.f16.f16.f32 "
        "{%0,%1,%2,%3}, {%4,%5,%6,%7}, {%8,%9}, {%0,%1,%2,%3};"
        : "+f"(c[0]), "+f"(c[1]), "+f"(c[2]), "+f"(c[3])
        : "r"(a[0]), "r"(a[1]), "r"(a[2]), "r"(a[3]), "r"(b[0]), "r"(b[1]));
}
__device__ __forceinline__ float fast_sigmoid(float v) {
    return 1.f / (1.f + __expf(-v));
}

// ---------------- HMMA fp16 GEMM: C[M,*] = A[M,K] @ W[*,K]^T ----------------
// Block 128x128, k-tile 64, 8 warps, warp tile 64x32, 3-stage cp.async.
// blockIdx.z = K-split chunk (partial outputs at C + z*M*ldc).
#define BM 128
#define BN 128
#define BK 64
#define LDS_ROW 72
#define TILE_B (128 * LDS_ROW * 2)
#define STAGE_B (2 * TILE_B)
#define STAGES 3
#define SMEM_TOTAL (STAGES * STAGE_B)    // 110592

__device__ __forceinline__ void stage_load(uint32_t sbase,
    const __half* __restrict__ A, const __half* __restrict__ W,
    int k0, int lda, int tid)
{
    const __half* srcs[2] = {A, W};
    #pragma unroll
    for (int a = 0; a < 2; a++) {
        #pragma unroll
        for (int i = 0; i < 4; i++) {
            int idx = i * 256 + tid;
            int row = idx >> 3;
            int c8  = (idx & 7) * 8;
            cp16(sbase + a * TILE_B + row * (LDS_ROW * 2) + c8 * 2,
                 srcs[a] + (size_t)row * lda + k0 + c8);
        }
    }
}

template <typename TOut>
__global__ __launch_bounds__(256, 2) void gemm_tc(
    const __half* __restrict__ A, const __half* __restrict__ W,
    TOut* __restrict__ C, int M, int ldc, int lda, int Kchunk)
{
    extern __shared__ char smem[];
    uint32_t sb = smem_u32(smem);
    const int tid = threadIdx.x, wid = tid >> 5, lane = tid & 31;
    const int wm = wid >> 2, wn = wid & 3;
    const int m0 = blockIdx.y * BM, n0 = blockIdx.x * BN;

    const __half* Ap = A + (size_t)m0 * lda + (size_t)blockIdx.z * Kchunk;
    const __half* Wp = W + (size_t)n0 * lda + (size_t)blockIdx.z * Kchunk;
    TOut* Cp = C + (size_t)blockIdx.z * M * ldc;

    float acc[4][4][4];
    #pragma unroll
    for (int i = 0; i < 4; i++)
        #pragma unroll
        for (int j = 0; j < 4; j++)
            #pragma unroll
            for (int q = 0; q < 4; q++) acc[i][j][q] = 0.f;

    const int T = Kchunk / BK;
    stage_load(sb + 0 * STAGE_B, Ap, Wp, 0, lda, tid);
    cp_commit();
    stage_load(sb + 1 * STAGE_B, Ap, Wp, BK, lda, tid);
    cp_commit();

    const int l15 = lane & 15;
    const int a_khalf = (lane >> 4) & 1;
    const int b_grp = lane >> 3, b_r = lane & 7;
    const int b_row_off = ((b_grp >> 1) << 3) + b_r;
    const int b_kb = (b_grp & 1) * 16;

    for (int t = 0; t < T; t++) {
        cp_wait1();
        __syncthreads();
        if (t + 2 < T)
            stage_load(sb + ((t + 2) % STAGES) * STAGE_B, Ap, Wp,
                       (t + 2) * BK, lda, tid);
        cp_commit();

        uint32_t cur = sb + (t % STAGES) * STAGE_B;
        #pragma unroll
        for (int kk = 0; kk < 4; kk++) {
            uint32_t af[4][4], wf[2][4];
            #pragma unroll
            for (int mi = 0; mi < 4; mi++) {
                int row = wm * 64 + mi * 16 + l15;
                ldm_x4(af[mi], cur + row * (LDS_ROW * 2) + kk * 32 + a_khalf * 16);
            }
            #pragma unroll
            for (int n2 = 0; n2 < 2; n2++) {
                int row = wn * 32 + n2 * 16 + b_row_off;
                ldm_x4(wf[n2], cur + TILE_B + row * (LDS_ROW * 2) + kk * 32 + b_kb);
            }
            #pragma unroll
            for (int mi = 0; mi < 4; mi++)
                #pragma unroll
                for (int ni = 0; ni < 4; ni++)
                    mma_fp16(acc[mi][ni], af[mi], &wf[ni >> 1][(ni & 1) * 2]);
        }
    }

    const int g = lane >> 2, tq = lane & 3;
    #pragma unroll
    for (int mi = 0; mi < 4; mi++) {
        #pragma unroll
        for (int ni = 0; ni < 4; ni++) {
            int row = m0 + wm * 64 + mi * 16 + g;
            int col = n0 + wn * 32 + ni * 8 + tq * 2;
            if (sizeof(TOut) == 4) {
                *(float2*)((float*)Cp + (size_t)row * ldc + col) =
                    make_float2(acc[mi][ni][0], acc[mi][ni][1]);
                *(float2*)((float*)Cp + (size_t)(row + 8) * ldc + col) =
                    make_float2(acc[mi][ni][2], acc[mi][ni][3]);
            } else {
                __half2 h0 = __floats2half2_rn(acc[mi][ni][0], acc[mi][ni][1]);
                __half2 h1 = __floats2half2_rn(acc[mi][ni][2], acc[mi][ni][3]);
                *(uint32_t*)((__half*)Cp + (size_t)row * ldc + col) = *(uint32_t*)&h0;
                *(uint32_t*)((__half*)Cp + (size_t)(row + 8) * ldc + col) = *(uint32_t*)&h1;
            }
        }
    }
}

// ---------------- merged prep: cvt x | cvt w1 | cvt wo | build wcat --------
#define NB_X  (M_ * DM_ / 4 / 256)
#define NB_W1 (N1_ * DM_ / 4 / 256)
#define NB_WO (DM_ * DI_ / 4 / 256)
#define NB_WC (NC_ * DI_ / 4 / 256)
__global__ __launch_bounds__(256) void prep_all_kernel(
    const float* __restrict__ x, const float* __restrict__ w1,
    const float* __restrict__ wo,
    const float* __restrict__ dw, const float* __restrict__ bw,
    const float* __restrict__ cw)
{
    int blk = blockIdx.x;
    if (blk < NB_X + NB_W1 + NB_WO) {
        const float* src; __half* dst; int i;
        if (blk < NB_X) {
            src = x;  dst = g_xf;  i = blk * 256 + threadIdx.x;
        } else if (blk < NB_X + NB_W1) {
            src = w1; dst = g_w1;  i = (blk - NB_X) * 256 + threadIdx.x;
        } else {
            src = wo; dst = g_wo;  i = (blk - NB_X - NB_W1) * 256 + threadIdx.x;
        }
        float4 v = ((const float4*)src)[i];
        __half2 a = __floats2half2_rn(v.x, v.y);
        __half2 b = __floats2half2_rn(v.z, v.w);
        ((uint2*)dst)[i] = make_uint2(*(uint32_t*)&a, *(uint32_t*)&b);
    } else {
        int i = (blk - NB_X - NB_W1 - NB_WO) * 256 + threadIdx.x;
        int row = i / (DI_ / 4);
        int c4  = (i % (DI_ / 4)) * 4;
        float4 v;
        if (row < 16)       v = *(const float4*)(dw + (size_t)row * DI_ + c4);
        else if (row < 32)  v = *(const float4*)(bw + (size_t)(row - 16) * DI_ + c4);
        else if (row < 48)  v = *(const float4*)(cw + (size_t)(row - 32) * DI_ + c4);
        else if (row == 48) v = make_float4(1.f, 1.f, 1.f, 1.f);
        else                v = make_float4(0.f, 0.f, 0.f, 0.f);
        __half2 a = __floats2half2_rn(v.x, v.y);
        __half2 b = __floats2half2_rn(v.z, v.w);
        ((uint2*)g_wc)[i] = make_uint2(*(uint32_t*)&a, *(uint32_t*)&b);
    }
}

// ---------------- causal conv (DC=4) + silu, 4-l blocking, fp16 in/out ------
__global__ __launch_bounds__(256) void conv_silu_kernel(
    const float* __restrict__ cw, const float* __restrict__ cb)
{
    int gid = blockIdx.x * blockDim.x + threadIdx.x;
    if (gid >= (M_ / 4) * (DI_ / 4)) return;
    int iq = gid & (DI_ / 4 - 1);
    int rq = gid >> 9;
    int i  = iq * 4;
    int b  = rq >> 9;
    int l0 = (rq & 511) * 4;

    float4 bias = *(const float4*)(cb + i);
    float w[4][4];
    #pragma unroll
    for (int j = 0; j < 4; j++) {
        float4 t = *(const float4*)(cw + (i + j) * DC_);
        w[j][0] = t.x; w[j][1] = t.y; w[j][2] = t.z; w[j][3] = t.w;
    }

    float v[7][4];
    #pragma unroll
    for (int j = 0; j < 7; j++) {
        int ls = l0 + j - 3;
        if (ls >= 0) {
            uint2 raw = *(const uint2*)(g_xinner + (size_t)(b * L_ + ls) * N1_ + i);
            float2 a0 = __half22float2(*(__half2*)&raw.x);
            float2 a1 = __half22float2(*(__half2*)&raw.y);
            v[j][0] = a0.x; v[j][1] = a0.y; v[j][2] = a1.x; v[j][3] = a1.y;
        } else {
            v[j][0] = v[j][1] = v[j][2] = v[j][3] = 0.f;
        }
    }

    #pragma unroll
    for (int t = 0; t < 4; t++) {
        float acc[4] = {bias.x, bias.y, bias.z, bias.w};
        #pragma unroll
        for (int k = 0; k < DC_; k++) {
            acc[0] = fmaf(v[t + k][0], w[0][k], acc[0]);
            acc[1] = fmaf(v[t + k][1], w[1][k], acc[1]);
            acc[2] = fmaf(v[t + k][2], w[2][k], acc[2]);
            acc[3] = fmaf(v[t + k][3], w[3][k], acc[3]);
        }
        float f0 = acc[0] * fast_sigmoid(acc[0]);
        float f1 = acc[1] * fast_sigmoid(acc[1]);
        float f2 = acc[2] * fast_sigmoid(acc[2]);
        float f3 = acc[3] * fast_sigmoid(acc[3]);
        __half2 a = __floats2half2_rn(f0, f1);
        __half2 bb = __floats2half2_rn(f2, f3);
        size_t o = (size_t)(b * L_ + l0 + t) * (DI_ / 4) + iq;
        ((uint2*)g_xc16)[o] = make_uint2(*(uint32_t*)&a, *(uint32_t*)&bb);
    }
}

// ---------------- scan (gu fused): one block per (b,s), 128 threads ---------
__global__ __launch_bounds__(128) void scan2_kernel(
    const float* __restrict__ A_log, const float* __restrict__ delta_b)
{
    __shared__ float sG[L_], sU[L_], sC[L_];
    __shared__ float sA[128], sB[128];
    const int b = blockIdx.x >> 4, s = blockIdx.x & 15;
    const int tid = threadIdx.x;

    const float Aval = -expf(A_log[s]);
    const float dbias = delta_b[s];
    const float* d0 = g_dots;
    const float* d1 = g_dots + (size_t)M_ * NC_;

    for (int l = tid; l < L_; l += 128) {
        size_t ro = (size_t)(b * L_ + l) * NC_;
        float dd = d0[ro + s]      + d1[ro + s];
        float db = d0[ro + 16 + s] + d1[ro + 16 + s];
        float dc = d0[ro + 32 + s] + d1[ro + 32 + s];
        float rs = d0[ro + 48]     + d1[ro + 48];
        float z = dd + dbias;
        float delta = (z > 20.f) ? z : log1pf(expf(z));
        sG[l] = expf(delta * Aval);
        sU[l] = delta * db * (rs * (1.f / (float)DI_));
        sC[l] = dc;
    }
    __syncthreads();

    const int CH = L_ / 128;   // 16
    const int l0 = tid * CH;
    float A = 1.f, U = 0.f;
    #pragma unroll
    for (int i = 0; i < CH; i++) {
        float gv = sG[l0 + i];
        A *= gv;
        U = fmaf(gv, U, sU[l0 + i]);
    }
    sA[tid] = A; sB[tid] = U;
    __syncthreads();

    #pragma unroll
    for (int d = 1; d < 128; d <<= 1) {
        float a2 = sA[tid], u2 = sB[tid];
        float a1 = 1.f, u1 = 0.f;
        if (tid >= d) { a1 = sA[tid - d]; u1 = sB[tid - d]; }
        __syncthreads();
        sA[tid] = a2 * a1;
        sB[tid] = fmaf(a2, u1, u2);
        __syncthreads();
    }

    float h = (tid == 0) ? 0.f : sB[tid - 1];
    #pragma unroll
    for (int i = 0; i < CH; i++) {
        h = fmaf(sG[l0 + i], h, sU[l0 + i]);
        sU[l0 + i] = h * sC[l0 + i];
    }
    __syncthreads();
    const size_t base = (size_t)s * M_ + (size_t)b * L_;
    for (int i = tid; i < L_ / 4; i += 128)
        *(float4*)(g_hc + base + i * 4) = ((float4*)sU)[i];
}

// ---------------- yskip (fused ysum): one 512-thread block per row ----------
__global__ __launch_bounds__(512) void yskip_kernel(const float* __restrict__ Dp)
{
    __shared__ float ysh;
    const int r = blockIdx.x;
    const int tid = threadIdx.x;

    if (tid < 16) {
        float v = g_hc[(size_t)tid * M_ + r];
        #pragma unroll
        for (int o = 8; o >= 1; o >>= 1)
            v += __shfl_xor_sync(0x0000ffffu, v, o);
        if (tid == 0) ysh = v;
    }
    __syncthreads();
    float yv = ysh;

    int i = tid * 4;
    uint2 graw = *(const uint2*)(g_xinner + (size_t)r * N1_ + DI_ + i);
    float2 g0 = __half22float2(*(__half2*)&graw.x);
    float2 g1 = __half22float2(*(__half2*)&graw.y);
    uint2 xraw = ((const uint2*)g_xc16)[(size_t)r * (DI_ / 4) + tid];
    float2 x0 = __half22float2(*(__half2*)&xraw.x);
    float2 x1 = __half22float2(*(__half2*)&xraw.y);
    float4 dv = *(const float4*)(Dp + i);
    float f0 = fmaf(yv, g0.x * fast_sigmoid(g0.x), x0.x * dv.x);
    float f1 = fmaf(yv, g0.y * fast_sigmoid(g0.y), x0.y * dv.y);
    float f2 = fmaf(yv, g1.x * fast_sigmoid(g1.x), x1.x * dv.z);
    float f3 = fmaf(yv, g1.y * fast_sigmoid(g1.y), x1.y * dv.w);
    __half2 a = __floats2half2_rn(f0, f1);
    __half2 b = __floats2half2_rn(f2, f3);
    ((uint2*)g_ys)[(size_t)r * (DI_ / 4) + tid] = make_uint2(*(uint32_t*)&a, *(uint32_t*)&b);
}

// ---------------- launch ----------------
extern "C" void kernel_launch(void* const* d_in, const int* in_sizes, int n_in,
                              void* d_out, int out_size)
{
    const float* x          = (const float*)d_in[0];
    const float* in_proj_w  = (const float*)d_in[1];
    const float* conv_w     = (const float*)d_in[2];
    const float* conv_b     = (const float*)d_in[3];
    const float* A_log      = (const float*)d_in[4];
    const float* Dp         = (const float*)d_in[5];
    const float* delta_w    = (const float*)d_in[6];
    const float* delta_b    = (const float*)d_in[7];
    const float* B_w        = (const float*)d_in[8];
    const float* C_w        = (const float*)d_in[9];
    const float* out_proj_w = (const float*)d_in[10];
    float* out = (float*)d_out;

    __half *p_xinner, *p_xf, *p_w1, *p_wo, *p_wc, *p_ys, *p_xc16;
    float *p_dots;
    cudaGetSymbolAddress((void**)&p_xinner, g_xinner);
    cudaGetSymbolAddress((void**)&p_xf, g_xf);
    cudaGetSymbolAddress((void**)&p_w1, g_w1);
    cudaGetSymbolAddress((void**)&p_wo, g_wo);
    cudaGetSymbolAddress((void**)&p_wc, g_wc);
    cudaGetSymbolAddress((void**)&p_ys, g_ys);
    cudaGetSymbolAddress((void**)&p_xc16, g_xc16);
    cudaGetSymbolAddress((void**)&p_dots, g_dots);

    cudaFuncSetAttribute(gemm_tc<__half>, cudaFuncAttributeMaxDynamicSharedMemorySize, SMEM_TOTAL);
    cudaFuncSetAttribute(gemm_tc<float>,  cudaFuncAttributeMaxDynamicSharedMemorySize, SMEM_TOTAL);

    // 0) all prep in one kernel
    prep_all_kernel<<<NB_X + NB_W1 + NB_WO + NB_WC, 256>>>(
        x, in_proj_w, out_proj_w, delta_w, B_w, C_w);

    // 1) x_inner = x @ in_proj_w^T  [8192,4096]  (fp16 out)
    gemm_tc<__half><<<dim3(N1_ / BN, M_ / BM, 1), 256, SMEM_TOTAL>>>(
        p_xf, p_w1, p_xinner, M_, N1_, DM_, DM_);

    // 2) causal conv + silu (fp16 in/out, 4-l blocking)
    conv_silu_kernel<<<((M_ / 4) * (DI_ / 4) + 255) / 256, 256>>>(conv_w, conv_b);

    // 3) dots = x_conv @ wcat^T  [8192,128], K-split z=2 (partials)
    gemm_tc<float><<<dim3(1, M_ / BM, KZ_), 256, SMEM_TOTAL>>>(
        p_xc16, p_wc, p_dots, M_, NC_, DI_, DI_ / KZ_);

    // 4) scan (coefficient computation fused)
    scan2_kernel<<<B_ * DS_, 128>>>(A_log, delta_b);

    // 5) gate + skip fuse (ysum inlined) -> fp16
    yskip_kernel<<<M_, 512>>>(Dp);

    // 6) out = y_skip @ out_proj_w^T  [8192,1024]  (fp32 out)
    gemm_tc<float><<<dim3(DM_ / BN, M_ / BM, 1), 256, SMEM_TOTAL>>>(
        p_ys, p_wo, out, M_, DM_, DI_, DI_);
}

// round 16
// speedup vs baseline: 1.0755x; 1.0151x over previous
#include <cuda_runtime.h>
#include <cuda_fp16.h>
#include <math.h>
#include <stdint.h>

// ---------------- problem dims ----------------
#define B_   4
#define L_   2048
#define DM_  1024
#define DS_  16
#define DC_  4
#define DI_  2048
#define N1_  4096              // 2*DI
#define M_   (B_ * L_)         // 8192
#define NC_  64                // padded N for the dbc GEMM (49 used)
#define KZ_  2                 // K-split for dbc

// ---------------- scratch (__device__ globals, no allocation) ----------------
__device__ __half g_xinner[(size_t)M_ * N1_];    // fp16
__device__ __half g_xc16  [(size_t)M_ * DI_];    // fp16 x_conv
__device__ float g_dots  [(size_t)KZ_ * M_ * NC_];  // partial dots
__device__ float g_hc[M_ * DS_];   // h*C, s-major
__device__ __half g_xf [(size_t)M_  * DM_];
__device__ __half g_w1 [(size_t)N1_ * DM_];
__device__ __half g_wo [(size_t)DM_ * DI_];
__device__ __half g_wc [(size_t)NC_ * DI_];      // [deltaw;Bw;Cw;ones;0...]
__device__ __half g_ys [(size_t)M_  * DI_];

// ---------------- helpers ----------------
__device__ __forceinline__ uint32_t smem_u32(const void* p) {
    uint32_t a;
    asm("{ .reg .u64 t; cvta.to.shared.u64 t, %1; cvt.u32.u64 %0, t; }" : "=r"(a) : "l"(p));
    return a;
}
__device__ __forceinline__ void cp16(uint32_t dst, const void* src) {
    asm volatile("cp.async.cg.shared.global [%0], [%1], 16;" :: "r"(dst), "l"(src));
}
__device__ __forceinline__ void cp_commit() {
    asm volatile("cp.async.commit_group;" ::: "memory");
}
__device__ __forceinline__ void cp_wait1() {
    asm volatile("cp.async.wait_group 1;" ::: "memory");
}
__device__ __forceinline__ void ldm_x4(uint32_t* r, uint32_t addr) {
    asm volatile("ldmatrix.sync.aligned.m8n8.x4.shared.b16 {%0,%1,%2,%3}, [%4];"
        : "=r"(r[0]), "=r"(r[1]), "=r"(r[2]), "=r"(r[3]) : "r"(addr));
}
__device__ __forceinline__ void mma_fp16(float* c, const uint32_t* a, const uint32_t* b) {
    asm volatile(
        "mma.sync.aligned.m16n8k16.row.col.f32.f16.f16.f32 "
        "{%0,%1,%2,%3}, {%4,%5,%6,%7}, {%8,%9}, {%0,%1,%2,%3};"
        : "+f"(c[0]), "+f"(c[1]), "+f"(c[2]), "+f"(c[3])
        : "r"(a[0]), "r"(a[1]), "r"(a[2]), "r"(a[3]), "r"(b[0]), "r"(b[1]));
}
__device__ __forceinline__ float fast_sigmoid(float v) {
    return 1.f / (1.f + __expf(-v));
}

// ---------------- HMMA fp16 GEMM: C[M,*] = A[M,K] @ W[*,K]^T ----------------
// Block 128x128, k-tile 64, 8 warps, warp tile 64x32, 3-stage cp.async.
#define BM 128
#define BN 128
#define BK 64
#define LDS_ROW 72
#define TILE_B (128 * LDS_ROW * 2)
#define STAGE_B (2 * TILE_B)
#define STAGES 3
#define SMEM_TOTAL (STAGES * STAGE_B)    // 110592

__device__ __forceinline__ void stage_load(uint32_t sbase,
    const __half* __restrict__ A, const __half* __restrict__ W,
    int k0, int lda, int tid)
{
    const __half* srcs[2] = {A, W};
    #pragma unroll
    for (int a = 0; a < 2; a++) {
        #pragma unroll
        for (int i = 0; i < 4; i++) {
            int idx = i * 256 + tid;
            int row = idx >> 3;
            int c8  = (idx & 7) * 8;
            cp16(sbase + a * TILE_B + row * (LDS_ROW * 2) + c8 * 2,
                 srcs[a] + (size_t)row * lda + k0 + c8);
        }
    }
}

template <typename TOut>
__global__ __launch_bounds__(256, 2) void gemm_tc(
    const __half* __restrict__ A, const __half* __restrict__ W,
    TOut* __restrict__ C, int M, int ldc, int lda, int Kchunk)
{
    extern __shared__ char smem[];
    uint32_t sb = smem_u32(smem);
    const int tid = threadIdx.x, wid = tid >> 5, lane = tid & 31;
    const int wm = wid >> 2, wn = wid & 3;
    const int m0 = blockIdx.y * BM, n0 = blockIdx.x * BN;

    const __half* Ap = A + (size_t)m0 * lda;
    const __half* Wp = W + (size_t)n0 * lda;

    float acc[4][4][4];
    #pragma unroll
    for (int i = 0; i < 4; i++)
        #pragma unroll
        for (int j = 0; j < 4; j++)
            #pragma unroll
            for (int q = 0; q < 4; q++) acc[i][j][q] = 0.f;

    const int T = Kchunk / BK;
    stage_load(sb + 0 * STAGE_B, Ap, Wp, 0, lda, tid);
    cp_commit();
    stage_load(sb + 1 * STAGE_B, Ap, Wp, BK, lda, tid);
    cp_commit();

    const int l15 = lane & 15;
    const int a_khalf = (lane >> 4) & 1;
    const int b_grp = lane >> 3, b_r = lane & 7;
    const int b_row_off = ((b_grp >> 1) << 3) + b_r;
    const int b_kb = (b_grp & 1) * 16;

    for (int t = 0; t < T; t++) {
        cp_wait1();
        __syncthreads();
        if (t + 2 < T)
            stage_load(sb + ((t + 2) % STAGES) * STAGE_B, Ap, Wp,
                       (t + 2) * BK, lda, tid);
        cp_commit();

        uint32_t cur = sb + (t % STAGES) * STAGE_B;
        #pragma unroll
        for (int kk = 0; kk < 4; kk++) {
            uint32_t af[4][4], wf[2][4];
            #pragma unroll
            for (int mi = 0; mi < 4; mi++) {
                int row = wm * 64 + mi * 16 + l15;
                ldm_x4(af[mi], cur + row * (LDS_ROW * 2) + kk * 32 + a_khalf * 16);
            }
            #pragma unroll
            for (int n2 = 0; n2 < 2; n2++) {
                int row = wn * 32 + n2 * 16 + b_row_off;
                ldm_x4(wf[n2], cur + TILE_B + row * (LDS_ROW * 2) + kk * 32 + b_kb);
            }
            #pragma unroll
            for (int mi = 0; mi < 4; mi++)
                #pragma unroll
                for (int ni = 0; ni < 4; ni++)
                    mma_fp16(acc[mi][ni], af[mi], &wf[ni >> 1][(ni & 1) * 2]);
        }
    }

    const int g = lane >> 2, tq = lane & 3;
    #pragma unroll
    for (int mi = 0; mi < 4; mi++) {
        #pragma unroll
        for (int ni = 0; ni < 4; ni++) {
            int row = m0 + wm * 64 + mi * 16 + g;
            int col = n0 + wn * 32 + ni * 8 + tq * 2;
            if (sizeof(TOut) == 4) {
                *(float2*)((float*)C + (size_t)row * ldc + col) =
                    make_float2(acc[mi][ni][0], acc[mi][ni][1]);
                *(float2*)((float*)C + (size_t)(row + 8) * ldc + col) =
                    make_float2(acc[mi][ni][2], acc[mi][ni][3]);
            } else {
                __half2 h0 = __floats2half2_rn(acc[mi][ni][0], acc[mi][ni][1]);
                __half2 h1 = __floats2half2_rn(acc[mi][ni][2], acc[mi][ni][3]);
                *(uint32_t*)((__half*)C + (size_t)row * ldc + col) = *(uint32_t*)&h0;
                *(uint32_t*)((__half*)C + (size_t)(row + 8) * ldc + col) = *(uint32_t*)&h1;
            }
        }
    }
}

// ---------------- dbc GEMM: BM64 x BN64 x BK64, 8 warps (2m x 4n) ----------
// warp tile 32x16, blockIdx.z = K-split chunk, partial out at C + z*M*NC_.
#define DTILE_B (64 * LDS_ROW * 2)         // 9216
#define DSTAGE_B (2 * DTILE_B)
#define DSMEM_TOTAL (STAGES * DSTAGE_B)    // 55296

__device__ __forceinline__ void stage_load_dbc(uint32_t sbase,
    const __half* __restrict__ A, const __half* __restrict__ W,
    int k0, int lda, int tid)
{
    const __half* srcs[2] = {A, W};
    #pragma unroll
    for (int a = 0; a < 2; a++) {
        #pragma unroll
        for (int i = 0; i < 2; i++) {
            int idx = i * 256 + tid;        // 0..511
            int row = idx >> 3;             // 0..63
            int c8  = (idx & 7) * 8;
            cp16(sbase + a * DTILE_B + row * (LDS_ROW * 2) + c8 * 2,
                 srcs[a] + (size_t)row * lda + k0 + c8);
        }
    }
}

__global__ __launch_bounds__(256, 2) void gemm_dbc(
    const __half* __restrict__ A, const __half* __restrict__ W,
    float* __restrict__ C, int M, int lda, int Kchunk)
{
    extern __shared__ char smem[];
    uint32_t sb = smem_u32(smem);
    const int tid = threadIdx.x, wid = tid >> 5, lane = tid & 31;
    const int wm = wid >> 2, wn = wid & 3;        // 2m x 4n, warp 32x16
    const int m0 = blockIdx.y * 64;

    const __half* Ap = A + (size_t)m0 * lda + (size_t)blockIdx.z * Kchunk;
    const __half* Wp = W + (size_t)blockIdx.z * Kchunk;
    float* Cp = C + (size_t)blockIdx.z * M * NC_;

    float acc[2][2][4];
    #pragma unroll
    for (int i = 0; i < 2; i++)
        #pragma unroll
        for (int j = 0; j < 2; j++)
            #pragma unroll
            for (int q = 0; q < 4; q++) acc[i][j][q] = 0.f;

    const int T = Kchunk / BK;
    stage_load_dbc(sb + 0 * DSTAGE_B, Ap, Wp, 0, lda, tid);
    cp_commit();
    stage_load_dbc(sb + 1 * DSTAGE_B, Ap, Wp, BK, lda, tid);
    cp_commit();

    const int l15 = lane & 15;
    const int a_khalf = (lane >> 4) & 1;
    const int b_grp = lane >> 3, b_r = lane & 7;
    const int b_row_off = ((b_grp >> 1) << 3) + b_r;
    const int b_kb = (b_grp & 1) * 16;

    for (int t = 0; t < T; t++) {
        cp_wait1();
        __syncthreads();
        if (t + 2 < T)
            stage_load_dbc(sb + ((t + 2) % STAGES) * DSTAGE_B, Ap, Wp,
                           (t + 2) * BK, lda, tid);
        cp_commit();

        uint32_t cur = sb + (t % STAGES) * DSTAGE_B;
        #pragma unroll
        for (int kk = 0; kk < 4; kk++) {
            uint32_t af[2][4], wf[4];
            #pragma unroll
            for (int mi = 0; mi < 2; mi++) {
                int row = wm * 32 + mi * 16 + l15;
                ldm_x4(af[mi], cur + row * (LDS_ROW * 2) + kk * 32 + a_khalf * 16);
            }
            {
                int row = wn * 16 + b_row_off;
                ldm_x4(wf, cur + DTILE_B + row * (LDS_ROW * 2) + kk * 32 + b_kb);
            }
            #pragma unroll
            for (int mi = 0; mi < 2; mi++)
                #pragma unroll
                for (int ni = 0; ni < 2; ni++)
                    mma_fp16(acc[mi][ni], af[mi], &wf[ni * 2]);
        }
    }

    const int g = lane >> 2, tq = lane & 3;
    #pragma unroll
    for (int mi = 0; mi < 2; mi++) {
        #pragma unroll
        for (int ni = 0; ni < 2; ni++) {
            int row = m0 + wm * 32 + mi * 16 + g;
            int col = wn * 16 + ni * 8 + tq * 2;
            *(float2*)(Cp + (size_t)row * NC_ + col) =
                make_float2(acc[mi][ni][0], acc[mi][ni][1]);
            *(float2*)(Cp + (size_t)(row + 8) * NC_ + col) =
                make_float2(acc[mi][ni][2], acc[mi][ni][3]);
        }
    }
}

// ---------------- merged prep: cvt x | cvt w1 | cvt wo | build wcat --------
#define NB_X  (M_ * DM_ / 4 / 256)
#define NB_W1 (N1_ * DM_ / 4 / 256)
#define NB_WO (DM_ * DI_ / 4 / 256)
#define NB_WC (NC_ * DI_ / 4 / 256)     // 128
__global__ __launch_bounds__(256) void prep_all_kernel(
    const float* __restrict__ x, const float* __restrict__ w1,
    const float* __restrict__ wo,
    const float* __restrict__ dw, const float* __restrict__ bw,
    const float* __restrict__ cw)
{
    int blk = blockIdx.x;
    if (blk < NB_X + NB_W1 + NB_WO) {
        const float* src; __half* dst; int i;
        if (blk < NB_X) {
            src = x;  dst = g_xf;  i = blk * 256 + threadIdx.x;
        } else if (blk < NB_X + NB_W1) {
            src = w1; dst = g_w1;  i = (blk - NB_X) * 256 + threadIdx.x;
        } else {
            src = wo; dst = g_wo;  i = (blk - NB_X - NB_W1) * 256 + threadIdx.x;
        }
        float4 v = ((const float4*)src)[i];
        __half2 a = __floats2half2_rn(v.x, v.y);
        __half2 b = __floats2half2_rn(v.z, v.w);
        ((uint2*)dst)[i] = make_uint2(*(uint32_t*)&a, *(uint32_t*)&b);
    } else {
        int i = (blk - NB_X - NB_W1 - NB_WO) * 256 + threadIdx.x;
        int row = i / (DI_ / 4);
        int c4  = (i % (DI_ / 4)) * 4;
        float4 v;
        if (row < 16)       v = *(const float4*)(dw + (size_t)row * DI_ + c4);
        else if (row < 32)  v = *(const float4*)(bw + (size_t)(row - 16) * DI_ + c4);
        else if (row < 48)  v = *(const float4*)(cw + (size_t)(row - 32) * DI_ + c4);
        else if (row == 48) v = make_float4(1.f, 1.f, 1.f, 1.f);
        else                v = make_float4(0.f, 0.f, 0.f, 0.f);
        __half2 a = __floats2half2_rn(v.x, v.y);
        __half2 b = __floats2half2_rn(v.z, v.w);
        ((uint2*)g_wc)[i] = make_uint2(*(uint32_t*)&a, *(uint32_t*)&b);
    }
}

// ---------------- causal conv (DC=4) + silu, 4-l blocking, fp16 in/out ------
__global__ __launch_bounds__(256) void conv_silu_kernel(
    const float* __restrict__ cw, const float* __restrict__ cb)
{
    int gid = blockIdx.x * blockDim.x + threadIdx.x;
    if (gid >= (M_ / 4) * (DI_ / 4)) return;
    int iq = gid & (DI_ / 4 - 1);
    int rq = gid >> 9;
    int i  = iq * 4;
    int b  = rq >> 9;
    int l0 = (rq & 511) * 4;

    float4 bias = *(const float4*)(cb + i);
    float w[4][4];
    #pragma unroll
    for (int j = 0; j < 4; j++) {
        float4 t = *(const float4*)(cw + (i + j) * DC_);
        w[j][0] = t.x; w[j][1] = t.y; w[j][2] = t.z; w[j][3] = t.w;
    }

    float v[7][4];
    #pragma unroll
    for (int j = 0; j < 7; j++) {
        int ls = l0 + j - 3;
        if (ls >= 0) {
            uint2 raw = *(const uint2*)(g_xinner + (size_t)(b * L_ + ls) * N1_ + i);
            float2 a0 = __half22float2(*(__half2*)&raw.x);
            float2 a1 = __half22float2(*(__half2*)&raw.y);
            v[j][0] = a0.x; v[j][1] = a0.y; v[j][2] = a1.x; v[j][3] = a1.y;
        } else {
            v[j][0] = v[j][1] = v[j][2] = v[j][3] = 0.f;
        }
    }

    #pragma unroll
    for (int t = 0; t < 4; t++) {
        float acc[4] = {bias.x, bias.y, bias.z, bias.w};
        #pragma unroll
        for (int k = 0; k < DC_; k++) {
            acc[0] = fmaf(v[t + k][0], w[0][k], acc[0]);
            acc[1] = fmaf(v[t + k][1], w[1][k], acc[1]);
            acc[2] = fmaf(v[t + k][2], w[2][k], acc[2]);
            acc[3] = fmaf(v[t + k][3], w[3][k], acc[3]);
        }
        float f0 = acc[0] * fast_sigmoid(acc[0]);
        float f1 = acc[1] * fast_sigmoid(acc[1]);
        float f2 = acc[2] * fast_sigmoid(acc[2]);
        float f3 = acc[3] * fast_sigmoid(acc[3]);
        __half2 a = __floats2half2_rn(f0, f1);
        __half2 bb = __floats2half2_rn(f2, f3);
        size_t o = (size_t)(b * L_ + l0 + t) * (DI_ / 4) + iq;
        ((uint2*)g_xc16)[o] = make_uint2(*(uint32_t*)&a, *(uint32_t*)&bb);
    }
}

// ---------------- scan (gu fused): one block per (b,s), 128 threads ---------
__global__ __launch_bounds__(128) void scan2_kernel(
    const float* __restrict__ A_log, const float* __restrict__ delta_b)
{
    __shared__ float sG[L_], sU[L_], sC[L_];
    __shared__ float sA[128], sB[128];
    const int b = blockIdx.x >> 4, s = blockIdx.x & 15;
    const int tid = threadIdx.x;

    const float Aval = -expf(A_log[s]);
    const float dbias = delta_b[s];
    const float* d0 = g_dots;
    const float* d1 = g_dots + (size_t)M_ * NC_;

    for (int l = tid; l < L_; l += 128) {
        size_t ro = (size_t)(b * L_ + l) * NC_;
        float dd = d0[ro + s]      + d1[ro + s];
        float db = d0[ro + 16 + s] + d1[ro + 16 + s];
        float dc = d0[ro + 32 + s] + d1[ro + 32 + s];
        float rs = d0[ro + 48]     + d1[ro + 48];
        float z = dd + dbias;
        float delta = (z > 20.f) ? z : log1pf(expf(z));
        sG[l] = expf(delta * Aval);
        sU[l] = delta * db * (rs * (1.f / (float)DI_));
        sC[l] = dc;
    }
    __syncthreads();

    const int CH = L_ / 128;   // 16
    const int l0 = tid * CH;
    float A = 1.f, U = 0.f;
    #pragma unroll
    for (int i = 0; i < CH; i++) {
        float gv = sG[l0 + i];
        A *= gv;
        U = fmaf(gv, U, sU[l0 + i]);
    }
    sA[tid] = A; sB[tid] = U;
    __syncthreads();

    #pragma unroll
    for (int d = 1; d < 128; d <<= 1) {
        float a2 = sA[tid], u2 = sB[tid];
        float a1 = 1.f, u1 = 0.f;
        if (tid >= d) { a1 = sA[tid - d]; u1 = sB[tid - d]; }
        __syncthreads();
        sA[tid] = a2 * a1;
        sB[tid] = fmaf(a2, u1, u2);
        __syncthreads();
    }

    float h = (tid == 0) ? 0.f : sB[tid - 1];
    #pragma unroll
    for (int i = 0; i < CH; i++) {
        h = fmaf(sG[l0 + i], h, sU[l0 + i]);
        sU[l0 + i] = h * sC[l0 + i];
    }
    __syncthreads();
    const size_t base = (size_t)s * M_ + (size_t)b * L_;
    for (int i = tid; i < L_ / 4; i += 128)
        *(float4*)(g_hc + base + i * 4) = ((float4*)sU)[i];
}

// ---------------- yskip (fused ysum): one 512-thread block per row ----------
__global__ __launch_bounds__(512) void yskip_kernel(const float* __restrict__ Dp)
{
    __shared__ float ysh;
    const int r = blockIdx.x;
    const int tid = threadIdx.x;

    if (tid < 16) {
        float v = g_hc[(size_t)tid * M_ + r];
        #pragma unroll
        for (int o = 8; o >= 1; o >>= 1)
            v += __shfl_xor_sync(0x0000ffffu, v, o);
        if (tid == 0) ysh = v;
    }
    __syncthreads();
    float yv = ysh;

    int i = tid * 4;
    uint2 graw = *(const uint2*)(g_xinner + (size_t)r * N1_ + DI_ + i);
    float2 g0 = __half22float2(*(__half2*)&graw.x);
    float2 g1 = __half22float2(*(__half2*)&graw.y);
    uint2 xraw = ((const uint2*)g_xc16)[(size_t)r * (DI_ / 4) + tid];
    float2 x0 = __half22float2(*(__half2*)&xraw.x);
    float2 x1 = __half22float2(*(__half2*)&xraw.y);
    float4 dv = *(const float4*)(Dp + i);
    float f0 = fmaf(yv, g0.x * fast_sigmoid(g0.x), x0.x * dv.x);
    float f1 = fmaf(yv, g0.y * fast_sigmoid(g0.y), x0.y * dv.y);
    float f2 = fmaf(yv, g1.x * fast_sigmoid(g1.x), x1.x * dv.z);
    float f3 = fmaf(yv, g1.y * fast_sigmoid(g1.y), x1.y * dv.w);
    __half2 a = __floats2half2_rn(f0, f1);
    __half2 b = __floats2half2_rn(f2, f3);
    ((uint2*)g_ys)[(size_t)r * (DI_ / 4) + tid] = make_uint2(*(uint32_t*)&a, *(uint32_t*)&b);
}

// ---------------- launch ----------------
extern "C" void kernel_launch(void* const* d_in, const int* in_sizes, int n_in,
                              void* d_out, int out_size)
{
    const float* x          = (const float*)d_in[0];
    const float* in_proj_w  = (const float*)d_in[1];
    const float* conv_w     = (const float*)d_in[2];
    const float* conv_b     = (const float*)d_in[3];
    const float* A_log      = (const float*)d_in[4];
    const float* Dp         = (const float*)d_in[5];
    const float* delta_w    = (const float*)d_in[6];
    const float* delta_b    = (const float*)d_in[7];
    const float* B_w        = (const float*)d_in[8];
    const float* C_w        = (const float*)d_in[9];
    const float* out_proj_w = (const float*)d_in[10];
    float* out = (float*)d_out;

    __half *p_xinner, *p_xf, *p_w1, *p_wo, *p_wc, *p_ys, *p_xc16;
    float *p_dots;
    cudaGetSymbolAddress((void**)&p_xinner, g_xinner);
    cudaGetSymbolAddress((void**)&p_xf, g_xf);
    cudaGetSymbolAddress((void**)&p_w1, g_w1);
    cudaGetSymbolAddress((void**)&p_wo, g_wo);
    cudaGetSymbolAddress((void**)&p_wc, g_wc);
    cudaGetSymbolAddress((void**)&p_ys, g_ys);
    cudaGetSymbolAddress((void**)&p_xc16, g_xc16);
    cudaGetSymbolAddress((void**)&p_dots, g_dots);

    cudaFuncSetAttribute(gemm_tc<__half>, cudaFuncAttributeMaxDynamicSharedMemorySize, SMEM_TOTAL);
    cudaFuncSetAttribute(gemm_tc<float>,  cudaFuncAttributeMaxDynamicSharedMemorySize, SMEM_TOTAL);
    cudaFuncSetAttribute(gemm_dbc, cudaFuncAttributeMaxDynamicSharedMemorySize, DSMEM_TOTAL);

    // 0) all prep in one kernel
    prep_all_kernel<<<NB_X + NB_W1 + NB_WO + NB_WC, 256>>>(
        x, in_proj_w, out_proj_w, delta_w, B_w, C_w);

    // 1) x_inner = x @ in_proj_w^T  [8192,4096]  (fp16 out)
    gemm_tc<__half><<<dim3(N1_ / BN, M_ / BM, 1), 256, SMEM_TOTAL>>>(
        p_xf, p_w1, p_xinner, M_, N1_, DM_, DM_);

    // 2) causal conv + silu (fp16 in/out, 4-l blocking)
    conv_silu_kernel<<<((M_ / 4) * (DI_ / 4) + 255) / 256, 256>>>(conv_w, conv_b);

    // 3) dots = x_conv @ wcat^T  [8192,64], BM64 tiles, K-split z=2
    gemm_dbc<<<dim3(1, M_ / 64, KZ_), 256, DSMEM_TOTAL>>>(
        p_xc16, p_wc, p_dots, M_, DI_, DI_ / KZ_);

    // 4) scan (coefficient computation fused)
    scan2_kernel<<<B_ * DS_, 128>>>(A_log, delta_b);

    // 5) gate + skip fuse (ysum inlined) -> fp16
    yskip_kernel<<<M_, 512>>>(Dp);

    // 6) out = y_skip @ out_proj_w^T  [8192,1024]  (fp32 out)
    gemm_tc<float><<<dim3(DM_ / BN, M_ / BM, 1), 256, SMEM_TOTAL>>>(
        p_ys, p_wo, out, M_, DM_, DI_, DI_);
}